// round 11
// baseline (speedup 1.0000x reference)
#include <cuda_runtime.h>
#include <cuda_bf16.h>
#include <cstdint>

// ---------------- problem constants ----------------
#define NN     50000
#define EE     800000
#define HIDN   96
#define GK     128      // fp32 A row stride (x and acat both 128 wide)
#define NODEF  128
#define TEMPF  10

// ---------------- device scratch ----------------
__device__ __align__(16) float g_dinv [NN];
__device__ __align__(16) float g_hs   [NN * HIDN];
__device__ __align__(16) float g_acat [NN * GK];
__device__ __align__(16) float g_h2   [NN * HIDN];
__device__ int   g_cnt [NN];
__device__ int   g_row [NN];
__device__ int   g_woff[NN];
__device__ int   g_csr [EE];
__device__ int   g_bsum[256];
__device__ int   g_boff[256];
__device__ int   g_flag[2];   // [mode]: 1 => HMMA result bad, repair kernel recomputes
// B in m16n8k8 fragment order: uint per (kt,nt,lane); [0..6143]=hi, [6144..12287]=lo
__device__ __align__(16) uint32_t g_bf[12288];

// ---------------- helpers ----------------
__device__ __forceinline__ uint32_t pack2(float a, float b) {
    __nv_bfloat16 ha = __float2bfloat16_rn(a), hb = __float2bfloat16_rn(b);
    return (uint32_t)__bfloat16_as_ushort(ha) | ((uint32_t)__bfloat16_as_ushort(hb) << 16);
}

__device__ __forceinline__ void split2(float2 f, uint32_t& hi, uint32_t& lo) {
    uint32_t h = pack2(f.x, f.y);
    float hx = __uint_as_float(h << 16);          // low bf16 as f32
    float hy = __uint_as_float(h & 0xFFFF0000u);  // high bf16 as f32
    hi = h;
    lo = pack2(f.x - hx, f.y - hy);
}

// m16n8k8: A reg0 = row g (k pair), reg1 = row g+8; B 1 reg; C 4 regs
__device__ __forceinline__ void mma1688(float* c, uint32_t a0, uint32_t a1, uint32_t b0) {
    asm volatile(
        "mma.sync.aligned.m16n8k8.row.col.f32.bf16.bf16.f32 "
        "{%0,%1,%2,%3}, {%4,%5}, {%6}, {%0,%1,%2,%3};"
        : "+f"(c[0]), "+f"(c[1]), "+f"(c[2]), "+f"(c[3])
        : "r"(a0), "r"(a1), "r"(b0));
}

// ---------------- CSR build ----------------
__global__ void k_zero_cnt(int n) {
    int i = blockIdx.x * blockDim.x + threadIdx.x;
    if (i < n) g_cnt[i] = 0;
    if (i < 2) g_flag[i] = 0;
}

__global__ void k_count(const int* __restrict__ ei, int E) {
    int e = blockIdx.x * blockDim.x + threadIdx.x;
    if (e < E) atomicAdd(&g_cnt[ei[E + e]], 1);
}

__global__ void __launch_bounds__(256) k_scan_blk(int n) {
    __shared__ int ws[8];
    int tid = threadIdx.x, lane = tid & 31, w = tid >> 5;
    int i = blockIdx.x * 256 + tid;
    int v = (i < n) ? g_cnt[i] : 0;
    int x = v;
#pragma unroll
    for (int o = 1; o < 32; o <<= 1) {
        int y = __shfl_up_sync(0xffffffffu, x, o);
        if (lane >= o) x += y;
    }
    if (lane == 31) ws[w] = x;
    __syncthreads();
    if (tid < 8) {
        int y = ws[tid];
#pragma unroll
        for (int o = 1; o < 8; o <<= 1) {
            int z = __shfl_up_sync(0xffu, y, o);
            if ((int)tid >= o) y += z;
        }
        ws[tid] = y;
    }
    __syncthreads();
    int excl = x - v + (w ? ws[w - 1] : 0);
    if (i < n) g_row[i] = excl;
    if (tid == 0) g_bsum[blockIdx.x] = ws[7];
}

__global__ void __launch_bounds__(256) k_scan_top(int nb) {
    __shared__ int ws[8];
    int tid = threadIdx.x, lane = tid & 31, w = tid >> 5;
    int v = (tid < nb) ? g_bsum[tid] : 0;
    int x = v;
#pragma unroll
    for (int o = 1; o < 32; o <<= 1) {
        int y = __shfl_up_sync(0xffffffffu, x, o);
        if (lane >= o) x += y;
    }
    if (lane == 31) ws[w] = x;
    __syncthreads();
    if (tid < 8) {
        int y = ws[tid];
#pragma unroll
        for (int o = 1; o < 8; o <<= 1) {
            int z = __shfl_up_sync(0xffu, y, o);
            if ((int)tid >= o) y += z;
        }
        ws[tid] = y;
    }
    __syncthreads();
    int excl = x - v + (w ? ws[w - 1] : 0);
    if (tid < nb) g_boff[tid] = excl;
}

__global__ void k_scan_add(int n) {
    int i = blockIdx.x * blockDim.x + threadIdx.x;
    if (i >= n) return;
    int excl = g_row[i] + g_boff[i >> 8];
    g_row [i] = excl;
    g_woff[i] = excl;
    g_dinv[i] = rsqrtf((float)(g_cnt[i] + 1));   // +1 self loop
}

__global__ void k_fill(const int* __restrict__ ei, int E) {
    int e = blockIdx.x * blockDim.x + threadIdx.x;
    if (e >= E) return;
    int src = ei[e];
    int dst = ei[E + e];
    int pos = atomicAdd(&g_woff[dst], 1);
    g_csr[pos] = src;
}

// ---------------- pack B [Ksrc x 96] into m16n8k8 fragment order (bf16 hi/lo) -------
__global__ void k_packbf(const float* __restrict__ W, int Ksrc) {
    int idx = blockIdx.x * blockDim.x + threadIdx.x;
    if (idx >= 6144) return;
    int lane = idx & 31, t = idx >> 5;     // t in [0,192)
    int nt = t % 12, kt = t / 12;          // kt in [0,16)
    int g = lane >> 2, tig = lane & 3;
    int n  = nt * 8 + g;
    int k0 = kt * 8 + tig * 2;
    float w0 = (k0     < Ksrc) ? W[(size_t)k0       * HIDN + n] : 0.0f;
    float w1 = (k0 + 1 < Ksrc) ? W[(size_t)(k0 + 1) * HIDN + n] : 0.0f;
    uint32_t hi, lo;
    split2(make_float2(w0, w1), hi, lo);
    g_bf[idx]        = hi;
    g_bf[6144 + idx] = lo;
}

// ---------------- HMMA GEMM: C[128,96] = A[128x128] @ B (2-way bf16 split) ----------
// mode 0: A=A_ext(x);  g_hs[m] = dinv[m] * C[m]
// mode 1: A=g_acat;    g_h2[m] = relu(C[m] + b1)
// NOTE: A for mode 1 selected IN DEVICE CODE (host cannot pass __device__ symbols!)
__global__ void __launch_bounds__(256) k_mma(
    const float* __restrict__ A_ext,
    const float* __restrict__ b1,
    int mode, int M)
{
    __shared__ uint32_t sbf[6144];   // 24 KB static: one k-half (hi at 0, lo at 3072)

    const float* __restrict__ A = (mode == 0) ? A_ext : g_acat;

    int tid  = threadIdx.x;
    int w    = tid >> 5;
    int lane = tid & 31;
    int g    = lane >> 2;
    int tig  = lane & 3;
    int m0   = blockIdx.x * 128 + w * 16 + g;
    int m1   = m0 + 8;
    bool v0  = m0 < M, v1 = m1 < M;

    float acc[12][4];
#pragma unroll
    for (int nt = 0; nt < 12; nt++)
#pragma unroll
        for (int q = 0; q < 4; q++) acc[nt][q] = 0.0f;

    const float* a0p = A + (size_t)m0 * GK;
    const float* a1p = A + (size_t)m1 * GK;

    for (int st = 0; st < 2; st++) {
        __syncthreads();   // previous stage reads done before overwrite
        {
            const uint4* srcH = reinterpret_cast<const uint4*>(g_bf + st * 3072);
            const uint4* srcL = reinterpret_cast<const uint4*>(g_bf + 6144 + st * 3072);
            uint4* dstH = reinterpret_cast<uint4*>(sbf);
            uint4* dstL = reinterpret_cast<uint4*>(sbf + 3072);
#pragma unroll
            for (int i = tid; i < 768; i += 256) { dstH[i] = srcH[i]; dstL[i] = srcL[i]; }
        }
        __syncthreads();

#pragma unroll
        for (int kl = 0; kl < 8; kl++) {
            int c0 = (st * 8 + kl) * 8 + tig * 2;
            float2 z = make_float2(0.f, 0.f);
            float2 fa = v0 ? *reinterpret_cast<const float2*>(a0p + c0) : z;  // row g
            float2 fb = v1 ? *reinterpret_cast<const float2*>(a1p + c0) : z;  // row g+8
            uint32_t ah0, al0, ah1, al1;
            split2(fa, ah0, al0);
            split2(fb, ah1, al1);

            int eb = kl * 384 + lane;
#pragma unroll
            for (int nt = 0; nt < 12; nt++) {
                uint32_t bh = sbf[eb + nt * 32];
                uint32_t bl = sbf[3072 + eb + nt * 32];
                mma1688(acc[nt], ah0, ah1, bh);   // ah*bh
                mma1688(acc[nt], ah0, ah1, bl);   // ah*bl
                mma1688(acc[nt], al0, al1, bh);   // al*bh
            }
        }
    }

    if (mode == 0) {
        float s0 = v0 ? g_dinv[m0] : 0.0f;
        float s1 = v1 ? g_dinv[m1] : 0.0f;
#pragma unroll
        for (int nt = 0; nt < 12; nt++) {
            int col = nt * 8 + tig * 2;
            if (v0) *reinterpret_cast<float2*>(g_hs + (size_t)m0 * HIDN + col) =
                        make_float2(acc[nt][0] * s0, acc[nt][1] * s0);
            if (v1) *reinterpret_cast<float2*>(g_hs + (size_t)m1 * HIDN + col) =
                        make_float2(acc[nt][2] * s1, acc[nt][3] * s1);
        }
    } else {
#pragma unroll
        for (int nt = 0; nt < 12; nt++) {
            int col = nt * 8 + tig * 2;
            float bb0 = __ldg(b1 + col), bb1 = __ldg(b1 + col + 1);
            if (v0) *reinterpret_cast<float2*>(g_h2 + (size_t)m0 * HIDN + col) =
                        make_float2(fmaxf(acc[nt][0] + bb0, 0.0f),
                                    fmaxf(acc[nt][1] + bb1, 0.0f));
            if (v1) *reinterpret_cast<float2*>(g_h2 + (size_t)m1 * HIDN + col) =
                        make_float2(fmaxf(acc[nt][2] + bb0, 0.0f),
                                    fmaxf(acc[nt][3] + bb1, 0.0f));
        }
    }
}

// ---------------- verify: fp32-recompute 8 spread rows; flag on mismatch ------------
__global__ void k_verify(const float* __restrict__ x,
                         const float* __restrict__ W,
                         const float* __restrict__ bias,
                         int Ksrc, int mode) {
    int j = threadIdx.x;
    if (j >= 96) return;
    const float* A = (mode == 0) ? x : g_acat;
    const int rows[8] = {3, 77, 1234, 4321, 12345, 25013, 37777, 49999};
    bool bad = false;
#pragma unroll 1
    for (int r = 0; r < 8; r++) {
        int m = rows[r];
        float s = 0.0f;
        for (int k = 0; k < Ksrc; k++)
            s = fmaf(A[(size_t)m * GK + k], W[(size_t)k * HIDN + j], s);
        float ref, got;
        if (mode == 0) { ref = s * g_dinv[m];               got = g_hs[(size_t)m * HIDN + j]; }
        else           { ref = fmaxf(s + bias[j], 0.0f);    got = g_h2[(size_t)m * HIDN + j]; }
        if (fabsf(got - ref) > 1e-4f * (fabsf(ref) + 0.25f)) bad = true;
    }
    if (bad) atomicExch(&g_flag[mode], 1);
}

// ---------------- repair: proven fp32 GEMM (R5), runs only if flag set --------------
__global__ void __launch_bounds__(256) k_repair(
    const float* __restrict__ A_ext,
    const float* __restrict__ W,
    const float* __restrict__ bias,
    int Ksrc, int mode, int M)
{
    if (g_flag[mode] == 0) return;   // uniform branch: all threads exit together

    __shared__ float As[64][36];
    __shared__ float Bs[32][96];

    const float* __restrict__ A = (mode == 0) ? A_ext : g_acat;

    int tid = threadIdx.x;
    int tx = tid & 15;
    int ty = tid >> 4;
    int row0 = blockIdx.x * 64;

    float acc[4][6];
#pragma unroll
    for (int r = 0; r < 4; r++)
#pragma unroll
        for (int c = 0; c < 6; c++) acc[r][c] = 0.0f;

    for (int kc = 0; kc < 4; kc++) {
        int k0 = kc * 32;
#pragma unroll
        for (int i = tid; i < 64 * 8; i += 256) {
            int m = i >> 3, kq = i & 7;
            int gm = row0 + m;
            float4 v = make_float4(0.f, 0.f, 0.f, 0.f);
            if (gm < M)
                v = reinterpret_cast<const float4*>(A + (size_t)gm * GK + k0)[kq];
            *reinterpret_cast<float4*>(&As[m][kq * 4]) = v;
        }
#pragma unroll
        for (int i = tid; i < 32 * 24; i += 256) {
            int kk = i / 24, jq = i % 24;
            float4 v = make_float4(0.f, 0.f, 0.f, 0.f);
            if (k0 + kk < Ksrc)
                v = reinterpret_cast<const float4*>(W + (size_t)(k0 + kk) * HIDN)[jq];
            *reinterpret_cast<float4*>(&Bs[kk][jq * 4]) = v;
        }
        __syncthreads();

#pragma unroll
        for (int kk = 0; kk < 32; kk += 4) {
            float4 a[4];
#pragma unroll
            for (int r = 0; r < 4; r++)
                a[r] = *reinterpret_cast<const float4*>(&As[ty * 4 + r][kk]);
            float bv[4][6];
#pragma unroll
            for (int q = 0; q < 4; q++) {
                float2 t0 = *reinterpret_cast<const float2*>(&Bs[kk + q][tx * 6]);
                float2 t1 = *reinterpret_cast<const float2*>(&Bs[kk + q][tx * 6 + 2]);
                float2 t2 = *reinterpret_cast<const float2*>(&Bs[kk + q][tx * 6 + 4]);
                bv[q][0] = t0.x; bv[q][1] = t0.y;
                bv[q][2] = t1.x; bv[q][3] = t1.y;
                bv[q][4] = t2.x; bv[q][5] = t2.y;
            }
#pragma unroll
            for (int r = 0; r < 4; r++) {
                float av[4] = { a[r].x, a[r].y, a[r].z, a[r].w };
#pragma unroll
                for (int q = 0; q < 4; q++)
#pragma unroll
                    for (int c = 0; c < 6; c++)
                        acc[r][c] = fmaf(av[q], bv[q][c], acc[r][c]);
            }
        }
        __syncthreads();
    }

#pragma unroll
    for (int r = 0; r < 4; r++) {
        int m = row0 + ty * 4 + r;
        if (m < M) {
            if (mode == 0) {
                float s = g_dinv[m];
#pragma unroll
                for (int c = 0; c < 6; c++)
                    g_hs[(size_t)m * HIDN + tx * 6 + c] = acc[r][c] * s;
            } else {
#pragma unroll
                for (int c = 0; c < 6; c++) {
                    int j = tx * 6 + c;
                    g_h2[(size_t)m * HIDN + j] = fmaxf(acc[r][c] + bias[j], 0.0f);
                }
            }
        }
    }
}

// ---------------- gather segment-sum + fused acat pack (proven) ----------------
__global__ void __launch_bounds__(256) k_gather(
    const float* __restrict__ temporal,
    const float* __restrict__ b_gcn, int n)
{
    int gw   = (blockIdx.x * blockDim.x + threadIdx.x) >> 5;
    int lane = threadIdx.x & 31;
    if (gw >= n) return;
    int i = gw;

    float4 acc = make_float4(0.f, 0.f, 0.f, 0.f);
    if (lane < 24)
        acc = reinterpret_cast<const float4*>(g_hs)[(size_t)i * 24 + lane];  // self loop

    int start = g_row[i];
    int cnt   = g_cnt[i];
    for (int base = 0; base < cnt; base += 32) {
        int e = base + lane;
        int s = (e < cnt) ? g_csr[start + e] : 0;
        int m = min(32, cnt - base);
        int j = 0;
        for (; j + 2 <= m; j += 2) {
            int s0 = __shfl_sync(0xffffffffu, s, j);
            int s1 = __shfl_sync(0xffffffffu, s, j + 1);
            if (lane < 24) {
                float4 v0 = reinterpret_cast<const float4*>(g_hs)[(size_t)s0 * 24 + lane];
                float4 v1 = reinterpret_cast<const float4*>(g_hs)[(size_t)s1 * 24 + lane];
                acc.x += v0.x + v1.x; acc.y += v0.y + v1.y;
                acc.z += v0.z + v1.z; acc.w += v0.w + v1.w;
            }
        }
        if (j < m) {
            int s0 = __shfl_sync(0xffffffffu, s, j);
            if (lane < 24) {
                float4 v0 = reinterpret_cast<const float4*>(g_hs)[(size_t)s0 * 24 + lane];
                acc.x += v0.x; acc.y += v0.y; acc.z += v0.z; acc.w += v0.w;
            }
        }
    }

    float di = g_dinv[i];
    if (lane < 24) {
        float4 b = reinterpret_cast<const float4*>(b_gcn)[lane];
        float4 o;
        o.x = fmaxf(fmaf(di, acc.x, b.x), 0.0f);
        o.y = fmaxf(fmaf(di, acc.y, b.y), 0.0f);
        o.z = fmaxf(fmaf(di, acc.z, b.z), 0.0f);
        o.w = fmaxf(fmaf(di, acc.w, b.w), 0.0f);
        reinterpret_cast<float4*>(g_acat)[(size_t)i * 32 + lane] = o;
    } else {
#pragma unroll
        for (int q = 0; q < 4; q++) {
            int c = 96 + (lane - 24) * 4 + q;
            float v = (c < HIDN + TEMPF) ? temporal[(size_t)i * TEMPF + (c - HIDN)] : 0.0f;
            g_acat[(size_t)i * GK + c] = v;
        }
    }
}

// ---------------- final (proven): out[i] = relu(h2[i].W2[0:96] + x[i].W2[96:224] + b2)
__global__ void k_final(const float* __restrict__ x,
                        const float* __restrict__ W2,
                        const float* __restrict__ b2,
                        float* __restrict__ out, int n) {
    int t = blockIdx.x * blockDim.x + threadIdx.x;
    int i = t >> 5, lane = t & 31;
    if (i >= n) return;
    float acc = 0.0f;
    if (lane < 24) {
        float4 a = reinterpret_cast<const float4*>(g_h2)[(size_t)i * 24 + lane];
        float4 w = reinterpret_cast<const float4*>(W2)[lane];
        acc = a.x * w.x + a.y * w.y + a.z * w.z + a.w * w.w;
    }
    {
        float4 a = reinterpret_cast<const float4*>(x)[(size_t)i * 32 + lane];
        float4 w = reinterpret_cast<const float4*>(W2 + HIDN)[lane];
        acc += a.x * w.x + a.y * w.y + a.z * w.z + a.w * w.w;
    }
#pragma unroll
    for (int o = 16; o; o >>= 1) acc += __shfl_down_sync(0xffffffffu, acc, o);
    if (lane == 0) out[i] = fmaxf(acc + b2[0], 0.0f);
}

// ---------------- launch ----------------
extern "C" void kernel_launch(void* const* d_in, const int* in_sizes, int n_in,
                              void* d_out, int out_size) {
    const float* x        = (const float*)d_in[0];
    const int*   ei       = (const int*)  d_in[1];   // int32 (JAX x64 disabled)
    const float* temporal = (const float*)d_in[2];
    const float* W_gcn    = (const float*)d_in[3];
    const float* b_gcn    = (const float*)d_in[4];
    const float* W1       = (const float*)d_in[5];
    const float* b1       = (const float*)d_in[6];
    const float* W2       = (const float*)d_in[7];
    const float* b2       = (const float*)d_in[8];
    float*       out      = (float*)d_out;

    int N  = in_sizes[0] / NODEF;   // 50000
    int E  = in_sizes[1] / 2;       // 800000
    int nb = (N + 255) / 256;       // 196
    int ng = (N + 127) / 128;       // 391 HMMA tiles
    int nr = (N + 63)  / 64;        // 782 repair tiles
    const int KS2 = HIDN + TEMPF;   // 106

    k_zero_cnt <<<nb, 256>>>(N);
    k_count    <<<(E + 255) / 256, 256>>>(ei, E);
    k_scan_blk <<<nb, 256>>>(N);
    k_scan_top <<<1, 256>>>(nb);
    k_scan_add <<<nb, 256>>>(N);
    k_fill     <<<(E + 255) / 256, 256>>>(ei, E);

    // GEMM1: g_hs = dinv * (x @ W_gcn)
    k_packbf   <<<24, 256>>>(W_gcn, 128);
    k_mma      <<<ng, 256>>>(x, nullptr, 0, N);
    k_verify   <<<1, 96>>>(x, W_gcn, nullptr, 128, 0);
    k_repair   <<<nr, 256>>>(x, W_gcn, nullptr, 128, 0, N);

    k_gather   <<<(N * 32 + 255) / 256, 256>>>(temporal, b_gcn, N);   // g_acat

    // GEMM2: g_h2 = relu(acat @ W1 + b1)
    k_packbf   <<<24, 256>>>(W1, KS2);
    k_mma      <<<ng, 256>>>(nullptr, b1, 1, N);
    k_verify   <<<1, 96>>>(nullptr, W1, b1, KS2, 1);
    k_repair   <<<nr, 256>>>(nullptr, W1, b1, KS2, 1, N);

    k_final    <<<(N * 32 + 255) / 256, 256>>>(x, W2, b2, out, N);
}

// round 12
// speedup vs baseline: 1.6807x; 1.6807x over previous
#include <cuda_runtime.h>
#include <cuda_bf16.h>
#include <cstdint>

// ---------------- problem constants ----------------
#define NN     50000
#define EE     800000
#define HIDN   96
#define GK     128      // fp32 A row stride (x and acat both 128 wide)
#define NODEF  128
#define TEMPF  10

// ---------------- device scratch ----------------
__device__ __align__(16) float g_dinv [NN];
__device__ __align__(16) float g_hs   [NN * HIDN];
__device__ __align__(16) float g_acat [NN * GK];
__device__ __align__(16) float g_xw2  [NN];
__device__ int   g_cnt [NN];
__device__ int   g_row [NN];
__device__ int   g_woff[NN];
__device__ int   g_csr [EE];
__device__ int   g_bsum[256];
__device__ int   g_boff[256];
// B in m16n8k8 fragment order: uint per (kt,nt,lane); [0..6143]=hi, [6144..12287]=lo
__device__ __align__(16) uint32_t g_bf[12288];

// ---------------- helpers ----------------
__device__ __forceinline__ uint32_t pack2(float a, float b) {
    __nv_bfloat16 ha = __float2bfloat16_rn(a), hb = __float2bfloat16_rn(b);
    return (uint32_t)__bfloat16_as_ushort(ha) | ((uint32_t)__bfloat16_as_ushort(hb) << 16);
}

__device__ __forceinline__ void split2(float2 f, uint32_t& hi, uint32_t& lo) {
    uint32_t h = pack2(f.x, f.y);
    float hx = __uint_as_float(h << 16);          // low bf16 as f32
    float hy = __uint_as_float(h & 0xFFFF0000u);  // high bf16 as f32
    hi = h;
    lo = pack2(f.x - hx, f.y - hy);
}

// m16n8k8: A reg0 = row g (k pair), reg1 = row g+8; B 1 reg; C 4 regs
__device__ __forceinline__ void mma1688(float* c, uint32_t a0, uint32_t a1, uint32_t b0) {
    asm volatile(
        "mma.sync.aligned.m16n8k8.row.col.f32.bf16.bf16.f32 "
        "{%0,%1,%2,%3}, {%4,%5}, {%6}, {%0,%1,%2,%3};"
        : "+f"(c[0]), "+f"(c[1]), "+f"(c[2]), "+f"(c[3])
        : "r"(a0), "r"(a1), "r"(b0));
}

// ---------------- CSR build ----------------
__global__ void k_zero_cnt(int n) {
    int i = blockIdx.x * blockDim.x + threadIdx.x;
    if (i < n) g_cnt[i] = 0;
}

__global__ void k_count(const int* __restrict__ ei, int E) {
    int e = blockIdx.x * blockDim.x + threadIdx.x;
    if (e < E) atomicAdd(&g_cnt[ei[E + e]], 1);
}

__global__ void __launch_bounds__(256) k_scan_blk(int n) {
    __shared__ int ws[8];
    int tid = threadIdx.x, lane = tid & 31, w = tid >> 5;
    int i = blockIdx.x * 256 + tid;
    int v = (i < n) ? g_cnt[i] : 0;
    int x = v;
#pragma unroll
    for (int o = 1; o < 32; o <<= 1) {
        int y = __shfl_up_sync(0xffffffffu, x, o);
        if (lane >= o) x += y;
    }
    if (lane == 31) ws[w] = x;
    __syncthreads();
    if (tid < 8) {
        int y = ws[tid];
#pragma unroll
        for (int o = 1; o < 8; o <<= 1) {
            int z = __shfl_up_sync(0xffu, y, o);
            if ((int)tid >= o) y += z;
        }
        ws[tid] = y;
    }
    __syncthreads();
    int excl = x - v + (w ? ws[w - 1] : 0);
    if (i < n) g_row[i] = excl;
    if (tid == 0) g_bsum[blockIdx.x] = ws[7];
}

__global__ void __launch_bounds__(256) k_scan_top(int nb) {
    __shared__ int ws[8];
    int tid = threadIdx.x, lane = tid & 31, w = tid >> 5;
    int v = (tid < nb) ? g_bsum[tid] : 0;
    int x = v;
#pragma unroll
    for (int o = 1; o < 32; o <<= 1) {
        int y = __shfl_up_sync(0xffffffffu, x, o);
        if (lane >= o) x += y;
    }
    if (lane == 31) ws[w] = x;
    __syncthreads();
    if (tid < 8) {
        int y = ws[tid];
#pragma unroll
        for (int o = 1; o < 8; o <<= 1) {
            int z = __shfl_up_sync(0xffu, y, o);
            if ((int)tid >= o) y += z;
        }
        ws[tid] = y;
    }
    __syncthreads();
    int excl = x - v + (w ? ws[w - 1] : 0);
    if (tid < nb) g_boff[tid] = excl;
}

__global__ void k_scan_add(int n) {
    int i = blockIdx.x * blockDim.x + threadIdx.x;
    if (i >= n) return;
    int excl = g_row[i] + g_boff[i >> 8];
    g_row [i] = excl;
    g_woff[i] = excl;
    g_dinv[i] = rsqrtf((float)(g_cnt[i] + 1));   // +1 self loop
}

__global__ void k_fill(const int* __restrict__ ei, int E) {
    int e = blockIdx.x * blockDim.x + threadIdx.x;
    if (e >= E) return;
    int src = ei[e];
    int dst = ei[E + e];
    int pos = atomicAdd(&g_woff[dst], 1);
    g_csr[pos] = src;
}

// ---------------- xw2[i] = x[i] . W2[96:224] ----------------
__global__ void k_xw2(const float* __restrict__ x, const float* __restrict__ W2, int n) {
    int t = blockIdx.x * blockDim.x + threadIdx.x;
    int i = t >> 5, lane = t & 31;
    if (i >= n) return;
    float4 a = reinterpret_cast<const float4*>(x)[(size_t)i * 32 + lane];
    float4 wv = __ldg(reinterpret_cast<const float4*>(W2 + HIDN) + lane);
    float p = a.x * wv.x + a.y * wv.y + a.z * wv.z + a.w * wv.w;
#pragma unroll
    for (int o = 16; o; o >>= 1) p += __shfl_xor_sync(0xffffffffu, p, o);
    if (lane == 0) g_xw2[i] = p;
}

// ---------------- pack B [Ksrc x 96] into m16n8k8 fragment order (bf16 hi/lo) -------
__global__ void k_packbf(const float* __restrict__ W, int Ksrc) {
    int idx = blockIdx.x * blockDim.x + threadIdx.x;
    if (idx >= 6144) return;
    int lane = idx & 31, t = idx >> 5;     // t in [0,192)
    int nt = t % 12, kt = t / 12;          // kt in [0,16)
    int g = lane >> 2, tig = lane & 3;
    int n  = nt * 8 + g;
    int k0 = kt * 8 + tig * 2;
    float w0 = (k0     < Ksrc) ? W[(size_t)k0       * HIDN + n] : 0.0f;
    float w1 = (k0 + 1 < Ksrc) ? W[(size_t)(k0 + 1) * HIDN + n] : 0.0f;
    uint32_t hi, lo;
    split2(make_float2(w0, w1), hi, lo);
    g_bf[idx]        = hi;
    g_bf[6144 + idx] = lo;
}

// ---------------- HMMA GEMM: C[128,96] = A[128x128] @ B (2-way bf16 split) ----------
// mode 0: A=A_ext(x);  g_hs[m] = dinv[m] * C[m]
// mode 1: A=g_acat;    out[m] = relu( relu(C[m]+b1).W2[0:96] + xw2[m] + b2 )
// NOTE: A for mode 1 selected IN DEVICE CODE (host cannot pass __device__ symbols!)
__global__ void __launch_bounds__(256) k_mma(
    const float* __restrict__ A_ext,
    const float* __restrict__ b1,
    const float* __restrict__ W2,
    const float* __restrict__ b2,
    float* __restrict__ outp,
    int mode, int M)
{
    __shared__ uint32_t sbf[6144];   // 24 KB static: one k-half (hi at 0, lo at 3072)

    const float* __restrict__ A = (mode == 0) ? A_ext : g_acat;

    int tid  = threadIdx.x;
    int w    = tid >> 5;
    int lane = tid & 31;
    int g    = lane >> 2;
    int tig  = lane & 3;
    int m0   = blockIdx.x * 128 + w * 16 + g;
    int m1   = m0 + 8;
    bool v0  = m0 < M, v1 = m1 < M;

    float acc[12][4];
#pragma unroll
    for (int nt = 0; nt < 12; nt++)
#pragma unroll
        for (int q = 0; q < 4; q++) acc[nt][q] = 0.0f;

    const float* a0p = A + (size_t)m0 * GK;
    const float* a1p = A + (size_t)m1 * GK;

    for (int st = 0; st < 2; st++) {
        __syncthreads();   // previous stage reads done before overwrite
        {
            const uint4* srcH = reinterpret_cast<const uint4*>(g_bf + st * 3072);
            const uint4* srcL = reinterpret_cast<const uint4*>(g_bf + 6144 + st * 3072);
            uint4* dstH = reinterpret_cast<uint4*>(sbf);
            uint4* dstL = reinterpret_cast<uint4*>(sbf + 3072);
#pragma unroll
            for (int i = tid; i < 768; i += 256) { dstH[i] = srcH[i]; dstL[i] = srcL[i]; }
        }
        __syncthreads();

#pragma unroll
        for (int kl = 0; kl < 8; kl++) {
            int c0 = (st * 8 + kl) * 8 + tig * 2;
            float2 z = make_float2(0.f, 0.f);
            float2 fa = v0 ? *reinterpret_cast<const float2*>(a0p + c0) : z;  // row g
            float2 fb = v1 ? *reinterpret_cast<const float2*>(a1p + c0) : z;  // row g+8
            uint32_t ah0, al0, ah1, al1;
            split2(fa, ah0, al0);
            split2(fb, ah1, al1);

            int eb = kl * 384 + lane;
#pragma unroll
            for (int nt = 0; nt < 12; nt++) {
                uint32_t bh = sbf[eb + nt * 32];
                uint32_t bl = sbf[3072 + eb + nt * 32];
                mma1688(acc[nt], ah0, ah1, bh);   // ah*bh
                mma1688(acc[nt], ah0, ah1, bl);   // ah*bl
                mma1688(acc[nt], al0, al1, bh);   // al*bh
            }
        }
    }

    if (mode == 0) {
        float s0 = v0 ? g_dinv[m0] : 0.0f;
        float s1 = v1 ? g_dinv[m1] : 0.0f;
#pragma unroll
        for (int nt = 0; nt < 12; nt++) {
            int col = nt * 8 + tig * 2;
            if (v0) *reinterpret_cast<float2*>(g_hs + (size_t)m0 * HIDN + col) =
                        make_float2(acc[nt][0] * s0, acc[nt][1] * s0);
            if (v1) *reinterpret_cast<float2*>(g_hs + (size_t)m1 * HIDN + col) =
                        make_float2(acc[nt][2] * s1, acc[nt][3] * s1);
        }
    } else {
        // fused final: row dot with W2[0:96] after relu(+b1); reduce over tig lanes
        float p0 = 0.0f, p1 = 0.0f;
#pragma unroll
        for (int nt = 0; nt < 12; nt++) {
            int col = nt * 8 + tig * 2;
            float bb0 = __ldg(b1 + col), bb1 = __ldg(b1 + col + 1);
            float ww0 = __ldg(W2 + col), ww1 = __ldg(W2 + col + 1);
            p0 = fmaf(fmaxf(acc[nt][0] + bb0, 0.0f), ww0, p0);
            p0 = fmaf(fmaxf(acc[nt][1] + bb1, 0.0f), ww1, p0);
            p1 = fmaf(fmaxf(acc[nt][2] + bb0, 0.0f), ww0, p1);
            p1 = fmaf(fmaxf(acc[nt][3] + bb1, 0.0f), ww1, p1);
        }
        p0 += __shfl_xor_sync(0xffffffffu, p0, 1);
        p0 += __shfl_xor_sync(0xffffffffu, p0, 2);
        p1 += __shfl_xor_sync(0xffffffffu, p1, 1);
        p1 += __shfl_xor_sync(0xffffffffu, p1, 2);
        if (tig == 0) {
            float b2v = __ldg(b2);
            if (v0) outp[m0] = fmaxf(p0 + g_xw2[m0] + b2v, 0.0f);
            if (v1) outp[m1] = fmaxf(p1 + g_xw2[m1] + b2v, 0.0f);
        }
    }
}

// ---------------- gather segment-sum + fused acat pack (proven) ----------------
__global__ void __launch_bounds__(256) k_gather(
    const float* __restrict__ temporal,
    const float* __restrict__ b_gcn, int n)
{
    int gw   = (blockIdx.x * blockDim.x + threadIdx.x) >> 5;
    int lane = threadIdx.x & 31;
    if (gw >= n) return;
    int i = gw;

    float4 acc = make_float4(0.f, 0.f, 0.f, 0.f);
    if (lane < 24)
        acc = reinterpret_cast<const float4*>(g_hs)[(size_t)i * 24 + lane];  // self loop

    int start = g_row[i];
    int cnt   = g_cnt[i];
    for (int base = 0; base < cnt; base += 32) {
        int e = base + lane;
        int s = (e < cnt) ? g_csr[start + e] : 0;
        int m = min(32, cnt - base);
        int j = 0;
        for (; j + 2 <= m; j += 2) {
            int s0 = __shfl_sync(0xffffffffu, s, j);
            int s1 = __shfl_sync(0xffffffffu, s, j + 1);
            if (lane < 24) {
                float4 v0 = reinterpret_cast<const float4*>(g_hs)[(size_t)s0 * 24 + lane];
                float4 v1 = reinterpret_cast<const float4*>(g_hs)[(size_t)s1 * 24 + lane];
                acc.x += v0.x + v1.x; acc.y += v0.y + v1.y;
                acc.z += v0.z + v1.z; acc.w += v0.w + v1.w;
            }
        }
        if (j < m) {
            int s0 = __shfl_sync(0xffffffffu, s, j);
            if (lane < 24) {
                float4 v0 = reinterpret_cast<const float4*>(g_hs)[(size_t)s0 * 24 + lane];
                acc.x += v0.x; acc.y += v0.y; acc.z += v0.z; acc.w += v0.w;
            }
        }
    }

    float di = g_dinv[i];
    if (lane < 24) {
        float4 b = reinterpret_cast<const float4*>(b_gcn)[lane];
        float4 o;
        o.x = fmaxf(fmaf(di, acc.x, b.x), 0.0f);
        o.y = fmaxf(fmaf(di, acc.y, b.y), 0.0f);
        o.z = fmaxf(fmaf(di, acc.z, b.z), 0.0f);
        o.w = fmaxf(fmaf(di, acc.w, b.w), 0.0f);
        reinterpret_cast<float4*>(g_acat)[(size_t)i * 32 + lane] = o;
    } else {
#pragma unroll
        for (int q = 0; q < 4; q++) {
            int c = 96 + (lane - 24) * 4 + q;
            float v = (c < HIDN + TEMPF) ? temporal[(size_t)i * TEMPF + (c - HIDN)] : 0.0f;
            g_acat[(size_t)i * GK + c] = v;
        }
    }
}

// ---------------- launch ----------------
extern "C" void kernel_launch(void* const* d_in, const int* in_sizes, int n_in,
                              void* d_out, int out_size) {
    const float* x        = (const float*)d_in[0];
    const int*   ei       = (const int*)  d_in[1];   // int32 (JAX x64 disabled)
    const float* temporal = (const float*)d_in[2];
    const float* W_gcn    = (const float*)d_in[3];
    const float* b_gcn    = (const float*)d_in[4];
    const float* W1       = (const float*)d_in[5];
    const float* b1       = (const float*)d_in[6];
    const float* W2       = (const float*)d_in[7];
    const float* b2       = (const float*)d_in[8];
    float*       out      = (float*)d_out;

    int N  = in_sizes[0] / NODEF;   // 50000
    int E  = in_sizes[1] / 2;       // 800000
    int nb = (N + 255) / 256;       // 196
    int ng = (N + 127) / 128;       // 391 HMMA tiles
    const int KS2 = HIDN + TEMPF;   // 106

    k_zero_cnt <<<nb, 256>>>(N);
    k_count    <<<(E + 255) / 256, 256>>>(ei, E);
    k_scan_blk <<<nb, 256>>>(N);
    k_scan_top <<<1, 256>>>(nb);
    k_scan_add <<<nb, 256>>>(N);
    k_fill     <<<(E + 255) / 256, 256>>>(ei, E);

    // GEMM1: g_hs = dinv * (x @ W_gcn)
    k_packbf   <<<24, 256>>>(W_gcn, 128);
    k_mma      <<<ng, 256>>>(x, nullptr, nullptr, nullptr, nullptr, 0, N);
    k_xw2      <<<(N * 32 + 255) / 256, 256>>>(x, W2, N);

    k_gather   <<<(N * 32 + 255) / 256, 256>>>(temporal, b_gcn, N);   // g_acat

    // GEMM2 + fused final: out = relu(relu(acat@W1+b1).W2[0:96] + xw2 + b2)
    k_packbf   <<<24, 256>>>(W1, KS2);
    k_mma      <<<ng, 256>>>(nullptr, b1, W2, b2, out, 1, N);
}

// round 13
// speedup vs baseline: 1.7442x; 1.0378x over previous
#include <cuda_runtime.h>
#include <cuda_bf16.h>
#include <cstdint>

// ---------------- problem constants ----------------
#define NN     50000
#define EE     800000
#define HIDN   96
#define GK     128      // fp32 A row stride (x and acat both 128 wide)
#define NODEF  128
#define TEMPF  10

// ---------------- device scratch ----------------
__device__ __align__(16) float g_dinv [NN];
__device__ __align__(16) float g_hs   [NN * HIDN];
__device__ __align__(16) float g_acat [NN * GK];
__device__ __align__(16) float g_xw2  [NN];
__device__ int   g_cnt [NN];
__device__ int   g_row [NN];
__device__ int   g_woff[NN];
__device__ int   g_csr [EE];
__device__ int   g_bsum[256];
// B in m16n8k8 fragment order: uint per (kt,nt,lane); [0..6143]=hi, [6144..12287]=lo
__device__ __align__(16) uint32_t g_bf[12288];

// ---------------- helpers ----------------
__device__ __forceinline__ uint32_t pack2(float a, float b) {
    __nv_bfloat16 ha = __float2bfloat16_rn(a), hb = __float2bfloat16_rn(b);
    return (uint32_t)__bfloat16_as_ushort(ha) | ((uint32_t)__bfloat16_as_ushort(hb) << 16);
}

__device__ __forceinline__ void split2(float2 f, uint32_t& hi, uint32_t& lo) {
    uint32_t h = pack2(f.x, f.y);
    float hx = __uint_as_float(h << 16);          // low bf16 as f32
    float hy = __uint_as_float(h & 0xFFFF0000u);  // high bf16 as f32
    hi = h;
    lo = pack2(f.x - hx, f.y - hy);
}

// m16n8k8: A reg0 = row g (k pair), reg1 = row g+8; B 1 reg; C 4 regs
__device__ __forceinline__ void mma1688(float* c, uint32_t a0, uint32_t a1, uint32_t b0) {
    asm volatile(
        "mma.sync.aligned.m16n8k8.row.col.f32.bf16.bf16.f32 "
        "{%0,%1,%2,%3}, {%4,%5}, {%6}, {%0,%1,%2,%3};"
        : "+f"(c[0]), "+f"(c[1]), "+f"(c[2]), "+f"(c[3])
        : "r"(a0), "r"(a1), "r"(b0));
}

// ---------------- CSR build ----------------
__global__ void k_zero_cnt(int n) {
    int i = blockIdx.x * blockDim.x + threadIdx.x;
    if (i < n) g_cnt[i] = 0;
}

__global__ void k_count(const int* __restrict__ ei, int E) {
    int e = blockIdx.x * blockDim.x + threadIdx.x;
    if (e < E) atomicAdd(&g_cnt[ei[E + e]], 1);
}

__global__ void __launch_bounds__(256) k_scan_blk(int n) {
    __shared__ int ws[8];
    int tid = threadIdx.x, lane = tid & 31, w = tid >> 5;
    int i = blockIdx.x * 256 + tid;
    int v = (i < n) ? g_cnt[i] : 0;
    int x = v;
#pragma unroll
    for (int o = 1; o < 32; o <<= 1) {
        int y = __shfl_up_sync(0xffffffffu, x, o);
        if (lane >= o) x += y;
    }
    if (lane == 31) ws[w] = x;
    __syncthreads();
    if (tid < 8) {
        int y = ws[tid];
#pragma unroll
        for (int o = 1; o < 8; o <<= 1) {
            int z = __shfl_up_sync(0xffu, y, o);
            if ((int)tid >= o) y += z;
        }
        ws[tid] = y;
    }
    __syncthreads();
    int excl = x - v + (w ? ws[w - 1] : 0);
    if (i < n) g_row[i] = excl;
    if (tid == 0) g_bsum[blockIdx.x] = ws[7];
}

// fused: per-block offset = reduce of prior block sums; add; cursors; dinv
__global__ void __launch_bounds__(256) k_scan_add(int n) {
    __shared__ int ws[8];
    __shared__ int sOff;
    int tid = threadIdx.x, lane = tid & 31, w = tid >> 5;
    int v = (tid < blockIdx.x) ? g_bsum[tid] : 0;
#pragma unroll
    for (int o = 16; o; o >>= 1) v += __shfl_xor_sync(0xffffffffu, v, o);
    if (lane == 0) ws[w] = v;
    __syncthreads();
    if (tid == 0) {
        int s = 0;
#pragma unroll
        for (int q = 0; q < 8; q++) s += ws[q];
        sOff = s;
    }
    __syncthreads();
    int i = blockIdx.x * 256 + tid;
    if (i >= n) return;
    int excl = g_row[i] + sOff;
    g_row [i] = excl;
    g_woff[i] = excl;
    g_dinv[i] = rsqrtf((float)(g_cnt[i] + 1));   // +1 self loop
}

__global__ void k_fill(const int* __restrict__ ei, int E) {
    int e = blockIdx.x * blockDim.x + threadIdx.x;
    if (e >= E) return;
    int src = ei[e];
    int dst = ei[E + e];
    int pos = atomicAdd(&g_woff[dst], 1);
    g_csr[pos] = src;
}

// ---------------- pack B [Ksrc x 96] into m16n8k8 fragment order (bf16 hi/lo) -------
__global__ void k_packbf(const float* __restrict__ W, int Ksrc) {
    int idx = blockIdx.x * blockDim.x + threadIdx.x;
    if (idx >= 6144) return;
    int lane = idx & 31, t = idx >> 5;     // t in [0,192)
    int nt = t % 12, kt = t / 12;          // kt in [0,16)
    int g = lane >> 2, tig = lane & 3;
    int n  = nt * 8 + g;
    int k0 = kt * 8 + tig * 2;
    float w0 = (k0     < Ksrc) ? W[(size_t)k0       * HIDN + n] : 0.0f;
    float w1 = (k0 + 1 < Ksrc) ? W[(size_t)(k0 + 1) * HIDN + n] : 0.0f;
    uint32_t hi, lo;
    split2(make_float2(w0, w1), hi, lo);
    g_bf[idx]        = hi;
    g_bf[6144 + idx] = lo;
}

// ---------------- HMMA GEMM: C[128,96] = A[128x128] @ B (2-way bf16 split) ----------
// mode 0: A=A_ext(x);  g_hs[m] = dinv[m]*C[m]; ALSO g_xw2[m] = x[m].W2[96:224] (fused)
// mode 1: A=g_acat;    out[m] = relu( relu(C[m]+b1).W2[0:96] + xw2[m] + b2 )
// NOTE: A for mode 1 selected IN DEVICE CODE (host cannot pass __device__ symbols!)
__global__ void __launch_bounds__(256) k_mma(
    const float* __restrict__ A_ext,
    const float* __restrict__ b1,
    const float* __restrict__ W2,
    const float* __restrict__ b2,
    float* __restrict__ outp,
    int mode, int M)
{
    __shared__ uint32_t sbf[6144];   // 24 KB static: one k-half (hi at 0, lo at 3072)

    const float* __restrict__ A = (mode == 0) ? A_ext : g_acat;

    int tid  = threadIdx.x;
    int w    = tid >> 5;
    int lane = tid & 31;
    int g    = lane >> 2;
    int tig  = lane & 3;
    int m0   = blockIdx.x * 128 + w * 16 + g;
    int m1   = m0 + 8;
    bool v0  = m0 < M, v1 = m1 < M;

    float acc[12][4];
#pragma unroll
    for (int nt = 0; nt < 12; nt++)
#pragma unroll
        for (int q = 0; q < 4; q++) acc[nt][q] = 0.0f;

    float px0 = 0.0f, px1 = 0.0f;   // mode 0: partial x.W2[96:224]

    const float* a0p = A + (size_t)m0 * GK;
    const float* a1p = A + (size_t)m1 * GK;

    for (int st = 0; st < 2; st++) {
        __syncthreads();   // previous stage reads done before overwrite
        {
            const uint4* srcH = reinterpret_cast<const uint4*>(g_bf + st * 3072);
            const uint4* srcL = reinterpret_cast<const uint4*>(g_bf + 6144 + st * 3072);
            uint4* dstH = reinterpret_cast<uint4*>(sbf);
            uint4* dstL = reinterpret_cast<uint4*>(sbf + 3072);
#pragma unroll
            for (int i = tid; i < 768; i += 256) { dstH[i] = srcH[i]; dstL[i] = srcL[i]; }
        }
        __syncthreads();

#pragma unroll
        for (int kl = 0; kl < 8; kl++) {
            int c0 = (st * 8 + kl) * 8 + tig * 2;
            float2 z = make_float2(0.f, 0.f);
            float2 fa = v0 ? *reinterpret_cast<const float2*>(a0p + c0) : z;  // row g
            float2 fb = v1 ? *reinterpret_cast<const float2*>(a1p + c0) : z;  // row g+8
            if (mode == 0) {
                float wa = __ldg(W2 + HIDN + c0);
                float wb = __ldg(W2 + HIDN + c0 + 1);
                px0 = fmaf(fa.x, wa, fmaf(fa.y, wb, px0));
                px1 = fmaf(fb.x, wa, fmaf(fb.y, wb, px1));
            }
            uint32_t ah0, al0, ah1, al1;
            split2(fa, ah0, al0);
            split2(fb, ah1, al1);

            int eb = kl * 384 + lane;
#pragma unroll
            for (int nt = 0; nt < 12; nt++) {
                uint32_t bh = sbf[eb + nt * 32];
                uint32_t bl = sbf[3072 + eb + nt * 32];
                mma1688(acc[nt], ah0, ah1, bh);   // ah*bh
                mma1688(acc[nt], ah0, ah1, bl);   // ah*bl
                mma1688(acc[nt], al0, al1, bh);   // al*bh
            }
        }
    }

    if (mode == 0) {
        float s0 = v0 ? g_dinv[m0] : 0.0f;
        float s1 = v1 ? g_dinv[m1] : 0.0f;
#pragma unroll
        for (int nt = 0; nt < 12; nt++) {
            int col = nt * 8 + tig * 2;
            if (v0) *reinterpret_cast<float2*>(g_hs + (size_t)m0 * HIDN + col) =
                        make_float2(acc[nt][0] * s0, acc[nt][1] * s0);
            if (v1) *reinterpret_cast<float2*>(g_hs + (size_t)m1 * HIDN + col) =
                        make_float2(acc[nt][2] * s1, acc[nt][3] * s1);
        }
        // quad-reduce xw2 partials (lanes g*4+tig, xor within quad)
        px0 += __shfl_xor_sync(0xffffffffu, px0, 1);
        px0 += __shfl_xor_sync(0xffffffffu, px0, 2);
        px1 += __shfl_xor_sync(0xffffffffu, px1, 1);
        px1 += __shfl_xor_sync(0xffffffffu, px1, 2);
        if (tig == 0) {
            if (v0) g_xw2[m0] = px0;
            if (v1) g_xw2[m1] = px1;
        }
    } else {
        // fused final: row dot with W2[0:96] after relu(+b1); reduce over tig lanes
        float p0 = 0.0f, p1 = 0.0f;
#pragma unroll
        for (int nt = 0; nt < 12; nt++) {
            int col = nt * 8 + tig * 2;
            float bb0 = __ldg(b1 + col), bb1 = __ldg(b1 + col + 1);
            float ww0 = __ldg(W2 + col), ww1 = __ldg(W2 + col + 1);
            p0 = fmaf(fmaxf(acc[nt][0] + bb0, 0.0f), ww0, p0);
            p0 = fmaf(fmaxf(acc[nt][1] + bb1, 0.0f), ww1, p0);
            p1 = fmaf(fmaxf(acc[nt][2] + bb0, 0.0f), ww0, p1);
            p1 = fmaf(fmaxf(acc[nt][3] + bb1, 0.0f), ww1, p1);
        }
        p0 += __shfl_xor_sync(0xffffffffu, p0, 1);
        p0 += __shfl_xor_sync(0xffffffffu, p0, 2);
        p1 += __shfl_xor_sync(0xffffffffu, p1, 1);
        p1 += __shfl_xor_sync(0xffffffffu, p1, 2);
        if (tig == 0) {
            float b2v = __ldg(b2);
            if (v0) outp[m0] = fmaxf(p0 + g_xw2[m0] + b2v, 0.0f);
            if (v1) outp[m1] = fmaxf(p1 + g_xw2[m1] + b2v, 0.0f);
        }
    }
}

// ---------------- gather segment-sum + fused acat pack (proven) ----------------
__global__ void __launch_bounds__(256) k_gather(
    const float* __restrict__ temporal,
    const float* __restrict__ b_gcn, int n)
{
    int gw   = (blockIdx.x * blockDim.x + threadIdx.x) >> 5;
    int lane = threadIdx.x & 31;
    if (gw >= n) return;
    int i = gw;

    float4 acc = make_float4(0.f, 0.f, 0.f, 0.f);
    if (lane < 24)
        acc = reinterpret_cast<const float4*>(g_hs)[(size_t)i * 24 + lane];  // self loop

    int start = g_row[i];
    int cnt   = g_cnt[i];
    for (int base = 0; base < cnt; base += 32) {
        int e = base + lane;
        int s = (e < cnt) ? g_csr[start + e] : 0;
        int m = min(32, cnt - base);
        int j = 0;
        for (; j + 2 <= m; j += 2) {
            int s0 = __shfl_sync(0xffffffffu, s, j);
            int s1 = __shfl_sync(0xffffffffu, s, j + 1);
            if (lane < 24) {
                float4 v0 = reinterpret_cast<const float4*>(g_hs)[(size_t)s0 * 24 + lane];
                float4 v1 = reinterpret_cast<const float4*>(g_hs)[(size_t)s1 * 24 + lane];
                acc.x += v0.x + v1.x; acc.y += v0.y + v1.y;
                acc.z += v0.z + v1.z; acc.w += v0.w + v1.w;
            }
        }
        if (j < m) {
            int s0 = __shfl_sync(0xffffffffu, s, j);
            if (lane < 24) {
                float4 v0 = reinterpret_cast<const float4*>(g_hs)[(size_t)s0 * 24 + lane];
                acc.x += v0.x; acc.y += v0.y; acc.z += v0.z; acc.w += v0.w;
            }
        }
    }

    float di = g_dinv[i];
    if (lane < 24) {
        float4 b = reinterpret_cast<const float4*>(b_gcn)[lane];
        float4 o;
        o.x = fmaxf(fmaf(di, acc.x, b.x), 0.0f);
        o.y = fmaxf(fmaf(di, acc.y, b.y), 0.0f);
        o.z = fmaxf(fmaf(di, acc.z, b.z), 0.0f);
        o.w = fmaxf(fmaf(di, acc.w, b.w), 0.0f);
        reinterpret_cast<float4*>(g_acat)[(size_t)i * 32 + lane] = o;
    } else {
#pragma unroll
        for (int q = 0; q < 4; q++) {
            int c = 96 + (lane - 24) * 4 + q;
            float v = (c < HIDN + TEMPF) ? temporal[(size_t)i * TEMPF + (c - HIDN)] : 0.0f;
            g_acat[(size_t)i * GK + c] = v;
        }
    }
}

// ---------------- launch ----------------
extern "C" void kernel_launch(void* const* d_in, const int* in_sizes, int n_in,
                              void* d_out, int out_size) {
    const float* x        = (const float*)d_in[0];
    const int*   ei       = (const int*)  d_in[1];   // int32 (JAX x64 disabled)
    const float* temporal = (const float*)d_in[2];
    const float* W_gcn    = (const float*)d_in[3];
    const float* b_gcn    = (const float*)d_in[4];
    const float* W1       = (const float*)d_in[5];
    const float* b1       = (const float*)d_in[6];
    const float* W2       = (const float*)d_in[7];
    const float* b2       = (const float*)d_in[8];
    float*       out      = (float*)d_out;

    int N  = in_sizes[0] / NODEF;   // 50000
    int E  = in_sizes[1] / 2;       // 800000
    int nb = (N + 255) / 256;       // 196
    int ng = (N + 127) / 128;       // 391 HMMA tiles
    const int KS2 = HIDN + TEMPF;   // 106

    k_zero_cnt <<<nb, 256>>>(N);
    k_count    <<<(E + 255) / 256, 256>>>(ei, E);
    k_scan_blk <<<nb, 256>>>(N);
    k_scan_add <<<nb, 256>>>(N);
    k_fill     <<<(E + 255) / 256, 256>>>(ei, E);

    // GEMM1: g_hs = dinv * (x @ W_gcn); fused g_xw2 = x . W2[96:224]
    k_packbf   <<<24, 256>>>(W_gcn, 128);
    k_mma      <<<ng, 256>>>(x, nullptr, W2, nullptr, nullptr, 0, N);

    k_gather   <<<(N * 32 + 255) / 256, 256>>>(temporal, b_gcn, N);   // g_acat

    // GEMM2 + fused final: out = relu(relu(acat@W1+b1).W2[0:96] + xw2 + b2)
    k_packbf   <<<24, 256>>>(W1, KS2);
    k_mma      <<<ng, 256>>>(nullptr, b1, W2, b2, out, 1, N);
}